// round 15
// baseline (speedup 1.0000x reference)
#include <cuda_runtime.h>
#include <cuda_fp16.h>
#include <cstdint>
#include <math.h>

#define H_DIM 128
#define R_DIM 6
#define D_DIM 256
#define MAX_NODES 50000
#define CAP 128            // max edges per node bucket

// Scratch
__device__ __align__(128) float g_agg[(size_t)MAX_NODES * H_DIM];   // 25.6 MB
__device__ __align__(128) float g_y0 [(size_t)MAX_NODES * D_DIM];   // 51.2 MB
__device__ __align__(128) float g_y1 [(size_t)MAX_NODES * D_DIM];   // 51.2 MB
__device__ __align__(128) int   g_cnt[MAX_NODES];
__device__ __align__(128) int   g_eid[(size_t)MAX_NODES * CAP];     // 25.6 MB
// Pre-split weights (fp16 hi/lo): [0,32768) = W_up (256x128), then 3x Ws (256x256)
#define W_TOTAL (256*128 + 3*256*256)
__device__ __align__(128) __half g_whi[W_TOTAL];
__device__ __align__(128) __half g_wlo[W_TOTAL];

__device__ __forceinline__ uint32_t pack_h2(float a, float b) {
    __half2 v = __halves2half2(__float2half_rn(a), __float2half_rn(b));
    return *reinterpret_cast<uint32_t*>(&v);
}

// ---------------------------------------------------------------------------
// Prep kernels
// ---------------------------------------------------------------------------
__global__ void prep_w(const float* __restrict__ W_up, const float* __restrict__ Ws,
                       __half* __restrict__ whi, __half* __restrict__ wlo) {
    int i = blockIdx.x * blockDim.x + threadIdx.x;
    int stride = gridDim.x * blockDim.x;
    for (; i < W_TOTAL; i += stride) {
        float v = (i < 256 * 128) ? W_up[i] : Ws[i - 256 * 128];
        __half h = __float2half_rn(v);
        whi[i] = h;
        wlo[i] = __float2half_rn(v - __half2float(h));
    }
}

__global__ void zero_kernel(float4* __restrict__ p, int n4) {
    int i = blockIdx.x * blockDim.x + threadIdx.x;
    int stride = gridDim.x * blockDim.x;
    float4 z = make_float4(0.f, 0.f, 0.f, 0.f);
    for (; i < n4; i += stride) p[i] = z;
}

// ---------------------------------------------------------------------------
// Bucket build: eid[node*CAP + p] = edge
// ---------------------------------------------------------------------------
__global__ void scatter_kernel(const int* __restrict__ idx,
                               int* __restrict__ cnt,
                               int* __restrict__ eid, int E) {
    int e = blockIdx.x * blockDim.x + threadIdx.x;
    if (e < E) {
        int n = __ldg(idx + e);
        int p = atomicAdd(cnt + n, 1);
        if (p < CAP)
            eid[(size_t)n * CAP + p] = e;
    }
}

// ---------------------------------------------------------------------------
// Gather stage: warp per node. Lane owns 4 channels. No atomics.
// agg[node, ch] = sum_{e in bucket} (rbf[e] . W_rbf[ch]) * x[e, ch]
// ---------------------------------------------------------------------------
__global__ void __launch_bounds__(256)
gather_kernel(const float* __restrict__ x,
              const float* __restrict__ rbf,
              const int*   __restrict__ cnt,
              const int*   __restrict__ eid,
              const float* __restrict__ Wrbf,
              float*       __restrict__ agg,
              int N) {
    const int lane = threadIdx.x & 31;
    const int node = (blockIdx.x * blockDim.x + threadIdx.x) >> 5;
    if (node >= N) return;

    float w[4][6];
    #pragma unroll
    for (int j = 0; j < 4; ++j)
        #pragma unroll
        for (int r = 0; r < R_DIM; ++r)
            w[j][r] = __ldg(Wrbf + (lane * 4 + j) * R_DIM + r);

    const int c = __ldg(cnt + node);
    const int* ep = eid + (size_t)node * CAP;
    float a0 = 0.f, a1 = 0.f, a2 = 0.f, a3 = 0.f;

    int i = 0;
    for (; i + 2 <= c; i += 2) {
        int e0 = __ldg(ep + i), e1 = __ldg(ep + i + 1);
        const float2* rp0 = reinterpret_cast<const float2*>(rbf + (size_t)e0 * R_DIM);
        const float2* rp1 = reinterpret_cast<const float2*>(rbf + (size_t)e1 * R_DIM);
        float2 p01 = __ldg(rp0 + 0), p23 = __ldg(rp0 + 1), p45 = __ldg(rp0 + 2);
        float2 q01 = __ldg(rp1 + 0), q23 = __ldg(rp1 + 1), q45 = __ldg(rp1 + 2);
        float4 xv0 = __ldg(reinterpret_cast<const float4*>(x + (size_t)e0 * H_DIM) + lane);
        float4 xv1 = __ldg(reinterpret_cast<const float4*>(x + (size_t)e1 * H_DIM) + lane);

        float g0 = w[0][0]*p01.x + w[0][1]*p01.y + w[0][2]*p23.x + w[0][3]*p23.y + w[0][4]*p45.x + w[0][5]*p45.y;
        float g1 = w[1][0]*p01.x + w[1][1]*p01.y + w[1][2]*p23.x + w[1][3]*p23.y + w[1][4]*p45.x + w[1][5]*p45.y;
        float g2 = w[2][0]*p01.x + w[2][1]*p01.y + w[2][2]*p23.x + w[2][3]*p23.y + w[2][4]*p45.x + w[2][5]*p45.y;
        float g3 = w[3][0]*p01.x + w[3][1]*p01.y + w[3][2]*p23.x + w[3][3]*p23.y + w[3][4]*p45.x + w[3][5]*p45.y;
        a0 = fmaf(g0, xv0.x, a0); a1 = fmaf(g1, xv0.y, a1);
        a2 = fmaf(g2, xv0.z, a2); a3 = fmaf(g3, xv0.w, a3);

        float h0 = w[0][0]*q01.x + w[0][1]*q01.y + w[0][2]*q23.x + w[0][3]*q23.y + w[0][4]*q45.x + w[0][5]*q45.y;
        float h1 = w[1][0]*q01.x + w[1][1]*q01.y + w[1][2]*q23.x + w[1][3]*q23.y + w[1][4]*q45.x + w[1][5]*q45.y;
        float h2 = w[2][0]*q01.x + w[2][1]*q01.y + w[2][2]*q23.x + w[2][3]*q23.y + w[2][4]*q45.x + w[2][5]*q45.y;
        float h3 = w[3][0]*q01.x + w[3][1]*q01.y + w[3][2]*q23.x + w[3][3]*q23.y + w[3][4]*q45.x + w[3][5]*q45.y;
        a0 = fmaf(h0, xv1.x, a0); a1 = fmaf(h1, xv1.y, a1);
        a2 = fmaf(h2, xv1.z, a2); a3 = fmaf(h3, xv1.w, a3);
    }
    if (i < c) {
        int e0 = __ldg(ep + i);
        const float2* rp0 = reinterpret_cast<const float2*>(rbf + (size_t)e0 * R_DIM);
        float2 p01 = __ldg(rp0 + 0), p23 = __ldg(rp0 + 1), p45 = __ldg(rp0 + 2);
        float4 xv0 = __ldg(reinterpret_cast<const float4*>(x + (size_t)e0 * H_DIM) + lane);
        float g0 = w[0][0]*p01.x + w[0][1]*p01.y + w[0][2]*p23.x + w[0][3]*p23.y + w[0][4]*p45.x + w[0][5]*p45.y;
        float g1 = w[1][0]*p01.x + w[1][1]*p01.y + w[1][2]*p23.x + w[1][3]*p23.y + w[1][4]*p45.x + w[1][5]*p45.y;
        float g2 = w[2][0]*p01.x + w[2][1]*p01.y + w[2][2]*p23.x + w[2][3]*p23.y + w[2][4]*p45.x + w[2][5]*p45.y;
        float g3 = w[3][0]*p01.x + w[3][1]*p01.y + w[3][2]*p23.x + w[3][3]*p23.y + w[3][4]*p45.x + w[3][5]*p45.y;
        a0 = fmaf(g0, xv0.x, a0); a1 = fmaf(g1, xv0.y, a1);
        a2 = fmaf(g2, xv0.z, a2); a3 = fmaf(g3, xv0.w, a3);
    }

    reinterpret_cast<float4*>(agg + (size_t)node * H_DIM)[lane] =
        make_float4(a0, a1, a2, a3);
}

// ---------------------------------------------------------------------------
// fp16-split GEMM, 2 products (Ahi*Bhi + Ahi*Blo), f32 acc, K-chunk 64.
// (frozen from round 14: 425us total, rel_err 4.7e-4)
// ---------------------------------------------------------------------------
#define STRIDE_H 72            // halfwords per SMEM row (64 data + 8 pad)
#define ARR_HW   (128 * STRIDE_H)          // 9216 halfwords per array
#define SMEM_BYTES (3 * ARR_HW * 2)        // 55296 bytes (Ahi, Bhi, Blo)

__device__ __forceinline__ void mma_f16(float* d, const uint32_t* a, uint32_t b0, uint32_t b1) {
    asm("mma.sync.aligned.m16n8k16.row.col.f32.f16.f16.f32 "
        "{%0,%1,%2,%3}, {%4,%5,%6,%7}, {%8,%9}, {%0,%1,%2,%3};"
        : "+f"(d[0]), "+f"(d[1]), "+f"(d[2]), "+f"(d[3])
        : "r"(a[0]), "r"(a[1]), "r"(a[2]), "r"(a[3]), "r"(b0), "r"(b1));
}

template<int K_TOTAL, bool BIAS, bool SILU, bool PROJ>
__global__ void __launch_bounds__(256, 2)
gemm_mma(const float* __restrict__ A,
         const __half* __restrict__ Bhi,
         const __half* __restrict__ Blo,
         const float* __restrict__ bias,
         const float* __restrict__ wout,
         float* __restrict__ Y,
         int M) {
    extern __shared__ __align__(16) uint16_t sm[];
    uint16_t* sAhi = sm;
    uint16_t* sBhi = sm + ARR_HW;
    uint16_t* sBlo = sm + 2 * ARR_HW;

    const int tid  = threadIdx.x;
    const int wid  = tid >> 5, lane = tid & 31;
    const int g    = lane >> 2, t = lane & 3;
    const int m0   = blockIdx.x * 128;
    const int n0   = blockIdx.y * 128;
    const int wm   = (wid & 3) * 32;
    const int wn   = (wid >> 2) * 64;

    float acc[2][8][4];
    #pragma unroll
    for (int i = 0; i < 2; ++i)
        #pragma unroll
        for (int j = 0; j < 8; ++j)
            #pragma unroll
            for (int q = 0; q < 4; ++q) acc[i][j][q] = 0.f;

    const uint32_t* A32hi = reinterpret_cast<const uint32_t*>(sAhi);
    const uint32_t* B32hi = reinterpret_cast<const uint32_t*>(sBhi);
    const uint32_t* B32lo = reinterpret_cast<const uint32_t*>(sBlo);

    const int a_seg = tid & 15;
    const int a_rip = tid >> 4;
    const int b_seg = tid & 7;
    const int b_rip = tid >> 3;

    for (int c = 0; c < K_TOTAL / 64; ++c) {
        #pragma unroll
        for (int p = 0; p < 8; ++p) {
            const int row = p * 16 + a_rip;
            const int grow = m0 + row;
            float4 f = make_float4(0.f, 0.f, 0.f, 0.f);
            if (grow < M)
                f = *reinterpret_cast<const float4*>(A + (size_t)grow * K_TOTAL + c * 64 + a_seg * 4);
            uint2 Hv;
            Hv.x = pack_h2(f.x, f.y);
            Hv.y = pack_h2(f.z, f.w);
            *reinterpret_cast<uint2*>(sAhi + row * STRIDE_H + a_seg * 4) = Hv;
        }
        #pragma unroll
        for (int p = 0; p < 4; ++p) {
            const int row = p * 32 + b_rip;
            const size_t off = (size_t)(n0 + row) * K_TOTAL + c * 64 + b_seg * 8;
            uint4 bh = *reinterpret_cast<const uint4*>(Bhi + off);
            uint4 bl = *reinterpret_cast<const uint4*>(Blo + off);
            const int hw = row * STRIDE_H + b_seg * 8;
            *reinterpret_cast<uint4*>(sBhi + hw) = bh;
            *reinterpret_cast<uint4*>(sBlo + hw) = bl;
        }
        __syncthreads();

        #pragma unroll
        for (int ks = 0; ks < 4; ++ks) {
            const int kw = ks * 8;
            uint32_t ahi[2][4];
            #pragma unroll
            for (int i = 0; i < 2; ++i) {
                int r0 = (wm + i * 16 + g) * (STRIDE_H / 2) + kw + t;
                ahi[i][0] = A32hi[r0];        ahi[i][1] = A32hi[r0 + 8 * (STRIDE_H / 2)];
                ahi[i][2] = A32hi[r0 + 4];    ahi[i][3] = A32hi[r0 + 8 * (STRIDE_H / 2) + 4];
            }
            #pragma unroll
            for (int j = 0; j < 8; ++j) {
                int nb = (wn + j * 8 + g) * (STRIDE_H / 2) + kw + t;
                uint32_t bh0 = B32hi[nb], bh1 = B32hi[nb + 4];
                uint32_t bl0 = B32lo[nb], bl1 = B32lo[nb + 4];
                #pragma unroll
                for (int i = 0; i < 2; ++i) {
                    mma_f16(acc[i][j], ahi[i], bh0, bh1);
                    mma_f16(acc[i][j], ahi[i], bl0, bl1);
                }
            }
        }
        __syncthreads();
    }

    if (PROJ) {
        float s[4] = {0.f, 0.f, 0.f, 0.f};
        #pragma unroll
        for (int i = 0; i < 2; ++i)
            #pragma unroll
            for (int j = 0; j < 8; ++j) {
                int col = n0 + wn + j * 8 + t * 2;
                float w0 = __ldg(wout + col), w1 = __ldg(wout + col + 1);
                float b0 = BIAS ? __ldg(bias + col) : 0.f;
                float b1 = BIAS ? __ldg(bias + col + 1) : 0.f;
                float v0 = acc[i][j][0] + b0, v1 = acc[i][j][1] + b1;
                float v2 = acc[i][j][2] + b0, v3 = acc[i][j][3] + b1;
                if (SILU) {
                    v0 = v0 / (1.f + __expf(-v0)); v1 = v1 / (1.f + __expf(-v1));
                    v2 = v2 / (1.f + __expf(-v2)); v3 = v3 / (1.f + __expf(-v3));
                }
                s[i * 2 + 0] += v0 * w0 + v1 * w1;
                s[i * 2 + 1] += v2 * w0 + v3 * w1;
            }
        #pragma unroll
        for (int q = 0; q < 4; ++q) {
            s[q] += __shfl_xor_sync(0xffffffffu, s[q], 1);
            s[q] += __shfl_xor_sync(0xffffffffu, s[q], 2);
        }
        if (t == 0) {
            #pragma unroll
            for (int i = 0; i < 2; ++i) {
                int r0 = m0 + wm + i * 16 + g;
                if (r0 < M)
                    asm volatile("red.global.add.f32 [%0], %1;" :: "l"(Y + r0), "f"(s[i*2]) : "memory");
                if (r0 + 8 < M)
                    asm volatile("red.global.add.f32 [%0], %1;" :: "l"(Y + r0 + 8), "f"(s[i*2+1]) : "memory");
            }
        }
    } else {
        #pragma unroll
        for (int i = 0; i < 2; ++i) {
            int r0 = m0 + wm + i * 16 + g;
            #pragma unroll
            for (int j = 0; j < 8; ++j) {
                int col = n0 + wn + j * 8 + t * 2;
                float b0 = BIAS ? __ldg(bias + col) : 0.f;
                float b1 = BIAS ? __ldg(bias + col + 1) : 0.f;
                float v0 = acc[i][j][0] + b0, v1 = acc[i][j][1] + b1;
                float v2 = acc[i][j][2] + b0, v3 = acc[i][j][3] + b1;
                if (SILU) {
                    v0 = v0 / (1.f + __expf(-v0)); v1 = v1 / (1.f + __expf(-v1));
                    v2 = v2 / (1.f + __expf(-v2)); v3 = v3 / (1.f + __expf(-v3));
                }
                if (r0 < M)
                    *reinterpret_cast<float2*>(Y + (size_t)r0 * D_DIM + col) = make_float2(v0, v1);
                if (r0 + 8 < M)
                    *reinterpret_cast<float2*>(Y + (size_t)(r0 + 8) * D_DIM + col) = make_float2(v2, v3);
            }
        }
    }
}

// ---------------------------------------------------------------------------
// Launch
// Inputs: 0:x[E,128] 1:rbf[E,6] 2:i[E] 3:W_rbf[128,6] 4:W_up[256,128]
//         5:Ws[3,256,256] 6:bs[3,256] 7:W_out[1,256] (8:num_nodes)
// ---------------------------------------------------------------------------
extern "C" void kernel_launch(void* const* d_in, const int* in_sizes, int n_in,
                              void* d_out, int out_size) {
    const float* x     = (const float*)d_in[0];
    const float* rbf   = (const float*)d_in[1];
    const int*   idx   = (const int*)  d_in[2];
    const float* W_rbf = (const float*)d_in[3];
    const float* W_up  = (const float*)d_in[4];
    const float* Ws    = (const float*)d_in[5];
    const float* bs    = (const float*)d_in[6];
    const float* W_out = (const float*)d_in[7];
    float* out = (float*)d_out;

    const int E = in_sizes[2];
    const int M = out_size;

    float *agg, *y0, *y1;
    int *cnt, *eid;
    __half *whi, *wlo;
    cudaGetSymbolAddress((void**)&agg, g_agg);
    cudaGetSymbolAddress((void**)&y0,  g_y0);
    cudaGetSymbolAddress((void**)&y1,  g_y1);
    cudaGetSymbolAddress((void**)&cnt, g_cnt);
    cudaGetSymbolAddress((void**)&eid, g_eid);
    cudaGetSymbolAddress((void**)&whi, g_whi);
    cudaGetSymbolAddress((void**)&wlo, g_wlo);

    cudaFuncSetAttribute(gemm_mma<128, false, false, false>, cudaFuncAttributeMaxDynamicSharedMemorySize, SMEM_BYTES);
    cudaFuncSetAttribute(gemm_mma<256, true,  true,  false>, cudaFuncAttributeMaxDynamicSharedMemorySize, SMEM_BYTES);
    cudaFuncSetAttribute(gemm_mma<256, true,  true,  true >, cudaFuncAttributeMaxDynamicSharedMemorySize, SMEM_BYTES);

    prep_w<<<224, 256>>>(W_up, Ws, whi, wlo);
    zero_kernel<<<64, 256>>>((float4*)cnt, M / 4);          // counters (int zeros)
    zero_kernel<<<128, 256>>>((float4*)out, M / 4);          // output

    // bucket build + gather (replaces atomic scatter edge stage)
    scatter_kernel<<<(E + 255) / 256, 256>>>(idx, cnt, eid, E);
    gather_kernel<<<(M * 32 + 255) / 256, 256>>>(x, rbf, cnt, eid, W_rbf, agg, M);

    const int tiles = (M + 127) / 128;
    dim3 grid(tiles, 2);
    const __half* whi_l = whi + 256 * 128;
    const __half* wlo_l = wlo + 256 * 128;

    // up-projection: y0 = agg @ W_up^T
    gemm_mma<128, false, false, false><<<grid, 256, SMEM_BYTES>>>(agg, whi, wlo, nullptr, nullptr, y0, M);
    // layer 0: y1 = silu(y0 @ W0^T + b0)
    gemm_mma<256, true, true, false><<<grid, 256, SMEM_BYTES>>>(y0, whi_l + 0*65536, wlo_l + 0*65536, bs + 0*D_DIM, nullptr, y1, M);
    // layer 1: y0 = silu(y1 @ W1^T + b1)
    gemm_mma<256, true, true, false><<<grid, 256, SMEM_BYTES>>>(y1, whi_l + 1*65536, wlo_l + 1*65536, bs + 1*D_DIM, nullptr, y0, M);
    // layer 2 + fused projection into out
    gemm_mma<256, true, true, true ><<<grid, 256, SMEM_BYTES>>>(y0, whi_l + 2*65536, wlo_l + 2*65536, bs + 2*D_DIM, W_out, out, M);
}

// round 16
// speedup vs baseline: 1.2172x; 1.2172x over previous
#include <cuda_runtime.h>
#include <cuda_fp16.h>
#include <cstdint>
#include <math.h>

#define H_DIM 128
#define R_DIM 6
#define D_DIM 256
#define MAX_NODES 50000

// Scratch
__device__ __align__(128) float  g_agg[(size_t)MAX_NODES * H_DIM];   // 25.6 MB
__device__ __align__(128) __half g_y0 [(size_t)MAX_NODES * D_DIM];   // 25.6 MB
__device__ __align__(128) __half g_y1 [(size_t)MAX_NODES * D_DIM];   // 25.6 MB
// Pre-split weights (fp16 hi/lo): [0,32768) = W_up (256x128), then 3x Ws (256x256)
#define W_TOTAL (256*128 + 3*256*256)
__device__ __align__(128) __half g_whi[W_TOTAL];
__device__ __align__(128) __half g_wlo[W_TOTAL];

__device__ __forceinline__ uint32_t pack_h2(float a, float b) {
    __half2 v = __halves2half2(__float2half_rn(a), __float2half_rn(b));
    return *reinterpret_cast<uint32_t*>(&v);
}

// ---------------------------------------------------------------------------
// Prep kernels
// ---------------------------------------------------------------------------
__global__ void prep_w(const float* __restrict__ W_up, const float* __restrict__ Ws,
                       __half* __restrict__ whi, __half* __restrict__ wlo) {
    int i = blockIdx.x * blockDim.x + threadIdx.x;
    int stride = gridDim.x * blockDim.x;
    for (; i < W_TOTAL; i += stride) {
        float v = (i < 256 * 128) ? W_up[i] : Ws[i - 256 * 128];
        __half h = __float2half_rn(v);
        whi[i] = h;
        wlo[i] = __float2half_rn(v - __half2float(h));
    }
}

// zero agg (n4a float4s) and out (n4o float4s) in one launch
__global__ void zero2_kernel(float4* __restrict__ a, int n4a,
                             float4* __restrict__ o, int n4o) {
    int i = blockIdx.x * blockDim.x + threadIdx.x;
    int stride = gridDim.x * blockDim.x;
    float4 z = make_float4(0.f, 0.f, 0.f, 0.f);
    for (int k = i; k < n4a; k += stride) a[k] = z;
    for (int k = i; k < n4o; k += stride) o[k] = z;
}

// ---------------------------------------------------------------------------
// Edge stage (round-5 proven best: 2 edges/warp-iter, 4ch/lane, red.v4)
// ---------------------------------------------------------------------------
__global__ void edge_kernel(const float* __restrict__ x,
                            const float* __restrict__ rbf,
                            const int*   __restrict__ idx,
                            const float* __restrict__ Wrbf,
                            float*       __restrict__ agg,
                            int E) {
    const int lane = threadIdx.x & 31;
    const int warp = (blockIdx.x * blockDim.x + threadIdx.x) >> 5;
    const int nwarps = (gridDim.x * blockDim.x) >> 5;

    float w[4][6];
    #pragma unroll
    for (int j = 0; j < 4; ++j)
        #pragma unroll
        for (int r = 0; r < R_DIM; ++r)
            w[j][r] = __ldg(Wrbf + (lane * 4 + j) * R_DIM + r);

    for (int e0 = warp * 2; e0 < E; e0 += nwarps * 2) {
        const int e1 = e0 + 1;
        const bool has1 = e1 < E;

        const float2* rp0 = reinterpret_cast<const float2*>(rbf + (size_t)e0 * R_DIM);
        float2 a01 = __ldg(rp0 + 0), a23 = __ldg(rp0 + 1), a45 = __ldg(rp0 + 2);
        int n0 = __ldg(idx + e0);
        float4 xv0 = __ldg(reinterpret_cast<const float4*>(x + (size_t)e0 * H_DIM) + lane);

        float2 b01 = a01, b23 = a23, b45 = a45;
        int n1 = n0;
        float4 xv1 = make_float4(0.f, 0.f, 0.f, 0.f);
        if (has1) {
            const float2* rp1 = reinterpret_cast<const float2*>(rbf + (size_t)e1 * R_DIM);
            b01 = __ldg(rp1 + 0); b23 = __ldg(rp1 + 1); b45 = __ldg(rp1 + 2);
            n1 = __ldg(idx + e1);
            xv1 = __ldg(reinterpret_cast<const float4*>(x + (size_t)e1 * H_DIM) + lane);
        }

        #pragma unroll
        for (int pass = 0; pass < 2; ++pass) {
            float2 r01 = pass ? b01 : a01;
            float2 r23 = pass ? b23 : a23;
            float2 r45 = pass ? b45 : a45;
            float4 xv  = pass ? xv1 : xv0;
            int node   = pass ? n1 : n0;
            if (pass && !has1) break;

            float g0 = w[0][0]*r01.x + w[0][1]*r01.y + w[0][2]*r23.x + w[0][3]*r23.y + w[0][4]*r45.x + w[0][5]*r45.y;
            float g1 = w[1][0]*r01.x + w[1][1]*r01.y + w[1][2]*r23.x + w[1][3]*r23.y + w[1][4]*r45.x + w[1][5]*r45.y;
            float g2 = w[2][0]*r01.x + w[2][1]*r01.y + w[2][2]*r23.x + w[2][3]*r23.y + w[2][4]*r45.x + w[2][5]*r45.y;
            float g3 = w[3][0]*r01.x + w[3][1]*r01.y + w[3][2]*r23.x + w[3][3]*r23.y + w[3][4]*r45.x + w[3][5]*r45.y;

            float vx = g0 * xv.x, vy = g1 * xv.y, vz = g2 * xv.z, vw = g3 * xv.w;
            float* dst = agg + (size_t)node * H_DIM + lane * 4;
            asm volatile("red.global.add.v4.f32 [%0], {%1, %2, %3, %4};"
                         :: "l"(dst), "f"(vx), "f"(vy), "f"(vz), "f"(vw) : "memory");
        }
    }
}

// ---------------------------------------------------------------------------
// fp16-split GEMM, 2 products (Ahi*Bhi + Ahi*Blo), f32 acc, K-chunk 64.
// A input: fp32 (AF32=true, converted at fill) or fp16 (raw copy).
// Output: fp16 (inter-layer) or fused projection (PROJ).
// CTA tile 128x128, 8 warps of 32x64, dynamic SMEM 54KB, 2 CTAs/SM.
// ---------------------------------------------------------------------------
#define STRIDE_H 72            // halfwords per SMEM row (64 data + 8 pad)
#define ARR_HW   (128 * STRIDE_H)          // 9216 halfwords per array
#define SMEM_BYTES (3 * ARR_HW * 2)        // 55296 bytes (Ahi, Bhi, Blo)

__device__ __forceinline__ void mma_f16(float* d, const uint32_t* a, uint32_t b0, uint32_t b1) {
    asm("mma.sync.aligned.m16n8k16.row.col.f32.f16.f16.f32 "
        "{%0,%1,%2,%3}, {%4,%5,%6,%7}, {%8,%9}, {%0,%1,%2,%3};"
        : "+f"(d[0]), "+f"(d[1]), "+f"(d[2]), "+f"(d[3])
        : "r"(a[0]), "r"(a[1]), "r"(a[2]), "r"(a[3]), "r"(b0), "r"(b1));
}

template<int K_TOTAL, bool AF32, bool BIAS, bool SILU, bool PROJ>
__global__ void __launch_bounds__(256, 2)
gemm_mma(const float* __restrict__ Af,
         const __half* __restrict__ Ah,
         const __half* __restrict__ Bhi,
         const __half* __restrict__ Blo,
         const float* __restrict__ bias,
         const float* __restrict__ wout,
         __half* __restrict__ Yh,
         float* __restrict__ Yproj,
         int M) {
    extern __shared__ __align__(16) uint16_t sm[];
    uint16_t* sAhi = sm;
    uint16_t* sBhi = sm + ARR_HW;
    uint16_t* sBlo = sm + 2 * ARR_HW;

    const int tid  = threadIdx.x;
    const int wid  = tid >> 5, lane = tid & 31;
    const int g    = lane >> 2, t = lane & 3;
    const int m0   = blockIdx.x * 128;
    const int n0   = blockIdx.y * 128;
    const int wm   = (wid & 3) * 32;
    const int wn   = (wid >> 2) * 64;

    float acc[2][8][4];
    #pragma unroll
    for (int i = 0; i < 2; ++i)
        #pragma unroll
        for (int j = 0; j < 8; ++j)
            #pragma unroll
            for (int q = 0; q < 4; ++q) acc[i][j][q] = 0.f;

    const uint32_t* A32hi = reinterpret_cast<const uint32_t*>(sAhi);
    const uint32_t* B32hi = reinterpret_cast<const uint32_t*>(sBhi);
    const uint32_t* B32lo = reinterpret_cast<const uint32_t*>(sBlo);

    // fp32 A fill: 16 threads/row (1 float4 each), 16 rows/pass, 8 passes
    const int a_seg = tid & 15;
    const int a_rip = tid >> 4;
    // fp16 A / B fill: 8 threads/row (1 uint4 = 8 halves), 32 rows/pass, 4 passes
    const int b_seg = tid & 7;
    const int b_rip = tid >> 3;

    for (int c = 0; c < K_TOTAL / 64; ++c) {
        // ---- fill A ----
        if (AF32) {
            #pragma unroll
            for (int p = 0; p < 8; ++p) {
                const int row = p * 16 + a_rip;
                const int grow = m0 + row;
                float4 f = make_float4(0.f, 0.f, 0.f, 0.f);
                if (grow < M)
                    f = *reinterpret_cast<const float4*>(Af + (size_t)grow * K_TOTAL + c * 64 + a_seg * 4);
                uint2 Hv;
                Hv.x = pack_h2(f.x, f.y);
                Hv.y = pack_h2(f.z, f.w);
                *reinterpret_cast<uint2*>(sAhi + row * STRIDE_H + a_seg * 4) = Hv;
            }
        } else {
            #pragma unroll
            for (int p = 0; p < 4; ++p) {
                const int row = p * 32 + b_rip;
                const int grow = m0 + row;
                uint4 v = make_uint4(0u, 0u, 0u, 0u);
                if (grow < M)
                    v = *reinterpret_cast<const uint4*>(Ah + (size_t)grow * K_TOTAL + c * 64 + b_seg * 8);
                *reinterpret_cast<uint4*>(sAhi + row * STRIDE_H + b_seg * 8) = v;
            }
        }
        // ---- fill B (hi + lo) ----
        #pragma unroll
        for (int p = 0; p < 4; ++p) {
            const int row = p * 32 + b_rip;
            const size_t off = (size_t)(n0 + row) * K_TOTAL + c * 64 + b_seg * 8;
            uint4 bh = *reinterpret_cast<const uint4*>(Bhi + off);
            uint4 bl = *reinterpret_cast<const uint4*>(Blo + off);
            const int hw = row * STRIDE_H + b_seg * 8;
            *reinterpret_cast<uint4*>(sBhi + hw) = bh;
            *reinterpret_cast<uint4*>(sBlo + hw) = bl;
        }
        __syncthreads();

        // ---- compute: 4 k16-steps x 2 products ----
        #pragma unroll
        for (int ks = 0; ks < 4; ++ks) {
            const int kw = ks * 8;
            uint32_t ahi[2][4];
            #pragma unroll
            for (int i = 0; i < 2; ++i) {
                int r0 = (wm + i * 16 + g) * (STRIDE_H / 2) + kw + t;
                ahi[i][0] = A32hi[r0];        ahi[i][1] = A32hi[r0 + 8 * (STRIDE_H / 2)];
                ahi[i][2] = A32hi[r0 + 4];    ahi[i][3] = A32hi[r0 + 8 * (STRIDE_H / 2) + 4];
            }
            #pragma unroll
            for (int j = 0; j < 8; ++j) {
                int nb = (wn + j * 8 + g) * (STRIDE_H / 2) + kw + t;
                uint32_t bh0 = B32hi[nb], bh1 = B32hi[nb + 4];
                uint32_t bl0 = B32lo[nb], bl1 = B32lo[nb + 4];
                #pragma unroll
                for (int i = 0; i < 2; ++i) {
                    mma_f16(acc[i][j], ahi[i], bh0, bh1);
                    mma_f16(acc[i][j], ahi[i], bl0, bl1);
                }
            }
        }
        __syncthreads();
    }

    // ---- epilogue ----
    if (PROJ) {
        float s[4] = {0.f, 0.f, 0.f, 0.f};
        #pragma unroll
        for (int i = 0; i < 2; ++i)
            #pragma unroll
            for (int j = 0; j < 8; ++j) {
                int col = n0 + wn + j * 8 + t * 2;
                float w0 = __ldg(wout + col), w1 = __ldg(wout + col + 1);
                float b0 = BIAS ? __ldg(bias + col) : 0.f;
                float b1 = BIAS ? __ldg(bias + col + 1) : 0.f;
                float v0 = acc[i][j][0] + b0, v1 = acc[i][j][1] + b1;
                float v2 = acc[i][j][2] + b0, v3 = acc[i][j][3] + b1;
                if (SILU) {
                    v0 = v0 / (1.f + __expf(-v0)); v1 = v1 / (1.f + __expf(-v1));
                    v2 = v2 / (1.f + __expf(-v2)); v3 = v3 / (1.f + __expf(-v3));
                }
                s[i * 2 + 0] += v0 * w0 + v1 * w1;
                s[i * 2 + 1] += v2 * w0 + v3 * w1;
            }
        #pragma unroll
        for (int q = 0; q < 4; ++q) {
            s[q] += __shfl_xor_sync(0xffffffffu, s[q], 1);
            s[q] += __shfl_xor_sync(0xffffffffu, s[q], 2);
        }
        if (t == 0) {
            #pragma unroll
            for (int i = 0; i < 2; ++i) {
                int r0 = m0 + wm + i * 16 + g;
                if (r0 < M)
                    asm volatile("red.global.add.f32 [%0], %1;" :: "l"(Yproj + r0), "f"(s[i*2]) : "memory");
                if (r0 + 8 < M)
                    asm volatile("red.global.add.f32 [%0], %1;" :: "l"(Yproj + r0 + 8), "f"(s[i*2+1]) : "memory");
            }
        }
    } else {
        #pragma unroll
        for (int i = 0; i < 2; ++i) {
            int r0 = m0 + wm + i * 16 + g;
            #pragma unroll
            for (int j = 0; j < 8; ++j) {
                int col = n0 + wn + j * 8 + t * 2;
                float b0 = BIAS ? __ldg(bias + col) : 0.f;
                float b1 = BIAS ? __ldg(bias + col + 1) : 0.f;
                float v0 = acc[i][j][0] + b0, v1 = acc[i][j][1] + b1;
                float v2 = acc[i][j][2] + b0, v3 = acc[i][j][3] + b1;
                if (SILU) {
                    v0 = v0 / (1.f + __expf(-v0)); v1 = v1 / (1.f + __expf(-v1));
                    v2 = v2 / (1.f + __expf(-v2)); v3 = v3 / (1.f + __expf(-v3));
                }
                // store y as fp16 (identical rounding to the consumer-side convert)
                if (r0 < M)
                    *reinterpret_cast<uint32_t*>(Yh + (size_t)r0 * D_DIM + col) = pack_h2(v0, v1);
                if (r0 + 8 < M)
                    *reinterpret_cast<uint32_t*>(Yh + (size_t)(r0 + 8) * D_DIM + col) = pack_h2(v2, v3);
            }
        }
    }
}

// ---------------------------------------------------------------------------
// Launch
// Inputs: 0:x[E,128] 1:rbf[E,6] 2:i[E] 3:W_rbf[128,6] 4:W_up[256,128]
//         5:Ws[3,256,256] 6:bs[3,256] 7:W_out[1,256] (8:num_nodes)
// ---------------------------------------------------------------------------
extern "C" void kernel_launch(void* const* d_in, const int* in_sizes, int n_in,
                              void* d_out, int out_size) {
    const float* x     = (const float*)d_in[0];
    const float* rbf   = (const float*)d_in[1];
    const int*   idx   = (const int*)  d_in[2];
    const float* W_rbf = (const float*)d_in[3];
    const float* W_up  = (const float*)d_in[4];
    const float* Ws    = (const float*)d_in[5];
    const float* bs    = (const float*)d_in[6];
    const float* W_out = (const float*)d_in[7];
    float* out = (float*)d_out;

    const int E = in_sizes[2];
    const int M = out_size;

    float* agg;
    __half *y0, *y1, *whi, *wlo;
    cudaGetSymbolAddress((void**)&agg, g_agg);
    cudaGetSymbolAddress((void**)&y0,  g_y0);
    cudaGetSymbolAddress((void**)&y1,  g_y1);
    cudaGetSymbolAddress((void**)&whi, g_whi);
    cudaGetSymbolAddress((void**)&wlo, g_wlo);

    cudaFuncSetAttribute(gemm_mma<128, true,  false, false, false>, cudaFuncAttributeMaxDynamicSharedMemorySize, SMEM_BYTES);
    cudaFuncSetAttribute(gemm_mma<256, false, true,  true,  false>, cudaFuncAttributeMaxDynamicSharedMemorySize, SMEM_BYTES);
    cudaFuncSetAttribute(gemm_mma<256, false, true,  true,  true >, cudaFuncAttributeMaxDynamicSharedMemorySize, SMEM_BYTES);

    prep_w<<<224, 256>>>(W_up, Ws, whi, wlo);
    zero2_kernel<<<1024, 256>>>((float4*)agg, M * H_DIM / 4, (float4*)out, M / 4);

    edge_kernel<<<1184, 256>>>(x, rbf, idx, W_rbf, agg, E);

    const int tiles = (M + 127) / 128;
    dim3 grid(tiles, 2);
    const __half* whi_l = whi + 256 * 128;
    const __half* wlo_l = wlo + 256 * 128;

    // up-projection (fp32 A): y0 = fp16(agg @ W_up^T)
    gemm_mma<128, true, false, false, false><<<grid, 256, SMEM_BYTES>>>(
        agg, nullptr, whi, wlo, nullptr, nullptr, y0, nullptr, M);
    // layer 0: y1 = fp16(silu(y0 @ W0^T + b0))
    gemm_mma<256, false, true, true, false><<<grid, 256, SMEM_BYTES>>>(
        nullptr, y0, whi_l + 0*65536, wlo_l + 0*65536, bs + 0*D_DIM, nullptr, y1, nullptr, M);
    // layer 1: y0 = fp16(silu(y1 @ W1^T + b1))
    gemm_mma<256, false, true, true, false><<<grid, 256, SMEM_BYTES>>>(
        nullptr, y1, whi_l + 1*65536, wlo_l + 1*65536, bs + 1*D_DIM, nullptr, y0, nullptr, M);
    // layer 2 + fused projection into out
    gemm_mma<256, false, true, true, true><<<grid, 256, SMEM_BYTES>>>(
        nullptr, y0, whi_l + 2*65536, wlo_l + 2*65536, bs + 2*D_DIM, W_out, nullptr, out, M);
}